// round 7
// baseline (speedup 1.0000x reference)
#include <cuda_runtime.h>

// Sequence_53300544143404: 2-layer LSTM (H=51), B=4096, T=1000 + 100 future.
// R6 (third submission of the R4 design; two prior GB300 container infra
// failures, source re-audited: no conditional barriers, no OOB, all 16B smem
// accesses aligned). Design: lane = batch row, warp = 4 h-indices. Weight
// loads are warp-uniform (hardware smem broadcast), value loads are single
// 128B coalesced wavefronts. Linear head folded into layer-2 pointwise as
// per-warp register partials. 128 CTAs x 416 threads (13 warps),
// 3 barriers/step, f32x2 FMAs, cell state register-resident for all 1100 steps.

#define Hh    51
#define BATCH 4096
#define T_IN  1000
#define FUT   100
#define T_TOT (T_IN + FUT)
#define NWARP 13            // 13 warps x 4 h = 52 h-slots (h=51 zero pad)
#define NTHR  (NWARP * 32)  // 416
#define RPC   32            // batch rows per CTA (= lanes)
#define NCTA  (BATCH / RPC) // 128

typedef unsigned long long ull;

struct SmemLayout {
    // Layer1 weights: [warp][k][16] ; 16 = 4 h x 4 gates (i,f,g,o).
    // k 0..50 = W_hh1 columns, k==51 = W_ih1 (x column).
    float WA[NWARP][52][16];
    // Layer2: k 0..50 = W_ih2 (h1 input), k==51 = 0 (x slot),
    //         k 52..102 = W_hh2 (h2 input), k==103 = 0 (pad row of B2).
    float WB[NWARP][104][16];
    // Ping-pong state buffers: B[p][k][lane]. 128B rows, coalesced.
    float B1[2][52][32];    // k 0..50 = h1, k 51 = x slot
    float B2[2][52][32];    // k 0..50 = h2, k 51 stays zero
    float BA[NWARP][16];    // b_ih1 + b_hh1, same [4h x 4g] layout
    float BB[NWARP][16];    // b_ih2 + b_hh2
    float P[NWARP][32];     // per-warp W_lin partials
};

__device__ __forceinline__ ull ffma2(ull a, ull b, ull c) {
    ull d;
    asm("fma.rn.f32x2 %0, %1, %2, %3;" : "=l"(d) : "l"(a), "l"(b), "l"(c));
    return d;
}
__device__ __forceinline__ ull pack2(float lo, float hi) {
    ull r; asm("mov.b64 %0, {%1, %2};" : "=l"(r) : "f"(lo), "f"(hi)); return r;
}
__device__ __forceinline__ void unpack2(ull v, float& lo, float& hi) {
    asm("mov.b64 {%0, %1}, %2;" : "=f"(lo), "=f"(hi) : "l"(v));
}
__device__ __forceinline__ float sig_(float x) {
    return __fdividef(1.0f, 1.0f + __expf(-x));
}
__device__ __forceinline__ float tanh_(float x) {
    float a = fabsf(x);
    float e = __expf(-2.0f * a);
    float r = __fdividef(1.0f - e, 1.0f + e);
    return copysignf(r, x);
}
__device__ __forceinline__ float cell_update(ull aIF, ull aGO, float& c) {
    float gi, gf, gg, go;
    unpack2(aIF, gi, gf);
    unpack2(aGO, gg, go);
    float cn = sig_(gf) * c + sig_(gi) * tanh_(gg);
    c = cn;
    return sig_(go) * tanh_(cn);
}

// Accumulators: [h0IF,h0GO,h1IF,h1GO,h2IF,h2GO,h3IF,h3GO]
struct Acc { ull a[8]; };

// nk iterations; per k: 64B warp-uniform weights (4 LDS.128, broadcast),
// 4B/lane value (1 coalesced LDS.32), 1 pack, 8 FFMA2.
__device__ __forceinline__ void gemm_block(const float* w, const float* v, int nk, Acc& A) {
    #pragma unroll 4
    for (int k = 0; k < nk; ++k) {
        ulonglong2 w0 = *reinterpret_cast<const ulonglong2*>(w);       // h0:(i,f),(g,o)
        ulonglong2 w1 = *reinterpret_cast<const ulonglong2*>(w + 4);   // h1
        ulonglong2 w2 = *reinterpret_cast<const ulonglong2*>(w + 8);   // h2
        ulonglong2 w3 = *reinterpret_cast<const ulonglong2*>(w + 12);  // h3
        float vv = *v;
        ull pv = pack2(vv, vv);
        w += 16; v += 32;
        A.a[0] = ffma2(w0.x, pv, A.a[0]);
        A.a[1] = ffma2(w0.y, pv, A.a[1]);
        A.a[2] = ffma2(w1.x, pv, A.a[2]);
        A.a[3] = ffma2(w1.y, pv, A.a[3]);
        A.a[4] = ffma2(w2.x, pv, A.a[4]);
        A.a[5] = ffma2(w2.y, pv, A.a[5]);
        A.a[6] = ffma2(w3.x, pv, A.a[6]);
        A.a[7] = ffma2(w3.y, pv, A.a[7]);
    }
}

extern __shared__ __align__(16) char smem_raw[];

__global__ __launch_bounds__(NTHR, 1)
void lstm_seq_kernel(const float* __restrict__ xin,
                     const float* __restrict__ W_ih1, const float* __restrict__ W_hh1,
                     const float* __restrict__ b_ih1, const float* __restrict__ b_hh1,
                     const float* __restrict__ W_ih2, const float* __restrict__ W_hh2,
                     const float* __restrict__ b_ih2, const float* __restrict__ b_hh2,
                     const float* __restrict__ W_lin, const float* __restrict__ b_lin,
                     float* __restrict__ out)
{
    SmemLayout* s = reinterpret_cast<SmemLayout*>(smem_raw);
    const int tid  = threadIdx.x;
    const int lane = tid & 31;
    const int wpid = tid >> 5;          // 0..12
    const int grow = blockIdx.x * RPC + lane;   // global batch row (always < BATCH)

    // ---------------- one-time smem staging ----------------
    for (int i = tid; i < NWARP * 52 * 16; i += NTHR) {
        int w = i / (52 * 16); int rem = i - w * 52 * 16; int k = rem >> 4; int j = rem & 15;
        int h = 4 * w + (j >> 2); int g = j & 3;
        float v = 0.f;
        if (h < Hh) {
            if (k < Hh)       v = W_hh1[(g * Hh + h) * Hh + k];
            else if (k == Hh) v = W_ih1[g * Hh + h];
        }
        s->WA[w][k][j] = v;
    }
    for (int i = tid; i < NWARP * 104 * 16; i += NTHR) {
        int w = i / (104 * 16); int rem = i - w * 104 * 16; int k = rem >> 4; int j = rem & 15;
        int h = 4 * w + (j >> 2); int g = j & 3;
        float v = 0.f;
        if (h < Hh) {
            if (k < Hh)                      v = W_ih2[(g * Hh + h) * Hh + k];
            else if (k >= 52 && k < 52 + Hh) v = W_hh2[(g * Hh + h) * Hh + (k - 52)];
        }
        s->WB[w][k][j] = v;
    }
    for (int i = tid; i < NWARP * 16; i += NTHR) {
        int w = i >> 4, j = i & 15;
        int h = 4 * w + (j >> 2); int g = j & 3;
        float a = 0.f, b = 0.f;
        if (h < Hh) {
            a = b_ih1[g * Hh + h] + b_hh1[g * Hh + h];
            b = b_ih2[g * Hh + h] + b_hh2[g * Hh + h];
        }
        s->BA[w][j] = a; s->BB[w][j] = b;
    }
    for (int i = tid; i < 2 * 52 * 32; i += NTHR) {
        s->B1[0][0][i] = 0.f;
        s->B2[0][0][i] = 0.f;
    }

    // W_lin coefficients for this warp's 4 h (register-resident)
    float wl0 = (4 * wpid + 0 < Hh) ? W_lin[4 * wpid + 0] : 0.f;
    float wl1 = (4 * wpid + 1 < Hh) ? W_lin[4 * wpid + 1] : 0.f;
    float wl2 = (4 * wpid + 2 < Hh) ? W_lin[4 * wpid + 2] : 0.f;
    float wl3 = (4 * wpid + 3 < Hh) ? W_lin[4 * wpid + 3] : 0.f;
    float blin = b_lin[0];

    float xv = 0.f;
    if (wpid == NWARP - 1) {
        // stage x[t=0] and prefetch x[t=1]
        s->B1[0][Hh][lane] = xin[grow * T_IN];
        xv = xin[grow * T_IN + 1];
    }
    __syncthreads();

    const float* waBase = &s->WA[wpid][0][0];
    const float* wbBase = &s->WB[wpid][0][0];

    float c1[4] = {0.f, 0.f, 0.f, 0.f};
    float c2[4] = {0.f, 0.f, 0.f, 0.f};
    float out_prev = 0.f;

    // ---------------- time loop ----------------
    for (int t = 0; t < T_TOT; ++t) {
        const int p = t & 1;
        const float* cur1 = &s->B1[p][0][0];
        float*       nxt1 = &s->B1[p ^ 1][0][0];
        const float* cur2 = &s->B2[p][0][0];
        float*       nxt2 = &s->B2[p ^ 1][0][0];

        // x for this step was staged into cur1 row 51 at the end of step t-1.
        Acc A;
        {
            // gates1 = [W_hh1 | W_ih1] @ [h1; x] + bias1
            ulonglong2 b0 = *reinterpret_cast<const ulonglong2*>(&s->BA[wpid][0]);
            ulonglong2 b1 = *reinterpret_cast<const ulonglong2*>(&s->BA[wpid][4]);
            ulonglong2 b2 = *reinterpret_cast<const ulonglong2*>(&s->BA[wpid][8]);
            ulonglong2 b3 = *reinterpret_cast<const ulonglong2*>(&s->BA[wpid][12]);
            A.a[0] = b0.x; A.a[1] = b0.y; A.a[2] = b1.x; A.a[3] = b1.y;
            A.a[4] = b2.x; A.a[5] = b2.y; A.a[6] = b3.x; A.a[7] = b3.y;
            gemm_block(waBase, cur1 + lane, 52, A);

            float h0 = cell_update(A.a[0], A.a[1], c1[0]);
            float h1 = cell_update(A.a[2], A.a[3], c1[1]);
            float h2 = cell_update(A.a[4], A.a[5], c1[2]);
            float h3 = cell_update(A.a[6], A.a[7], c1[3]);
            // Warp 12's h3 slot is h=51 -> zero weights/bias, h3==0; its write to
            // row 51 (x slot) is overwritten by the x-stage below before any
            // cross-warp read of that row as cur1 (barrier-ordered).
            nxt1[(4 * wpid + 0) * 32 + lane] = h0;
            nxt1[(4 * wpid + 1) * 32 + lane] = h1;
            nxt1[(4 * wpid + 2) * 32 + lane] = h2;
            nxt1[(4 * wpid + 3) * 32 + lane] = h3;
        }
        __syncthreads();   // S2: h1_new visible

        {
            // gates2 = [W_ih2 | W_hh2] @ [h1_new; h2] + bias2
            ulonglong2 b0 = *reinterpret_cast<const ulonglong2*>(&s->BB[wpid][0]);
            ulonglong2 b1 = *reinterpret_cast<const ulonglong2*>(&s->BB[wpid][4]);
            ulonglong2 b2 = *reinterpret_cast<const ulonglong2*>(&s->BB[wpid][8]);
            ulonglong2 b3 = *reinterpret_cast<const ulonglong2*>(&s->BB[wpid][12]);
            A.a[0] = b0.x; A.a[1] = b0.y; A.a[2] = b1.x; A.a[3] = b1.y;
            A.a[4] = b2.x; A.a[5] = b2.y; A.a[6] = b3.x; A.a[7] = b3.y;
            gemm_block(wbBase,            nxt1 + lane, 52, A);
            gemm_block(wbBase + 52 * 16,  cur2 + lane, 52, A);

            float h0 = cell_update(A.a[0], A.a[1], c2[0]);
            float h1 = cell_update(A.a[2], A.a[3], c2[1]);
            float h2 = cell_update(A.a[4], A.a[5], c2[2]);
            float h3 = cell_update(A.a[6], A.a[7], c2[3]);
            nxt2[(4 * wpid + 0) * 32 + lane] = h0;
            nxt2[(4 * wpid + 1) * 32 + lane] = h1;
            nxt2[(4 * wpid + 2) * 32 + lane] = h2;
            nxt2[(4 * wpid + 3) * 32 + lane] = h3;
            // fold linear head: per-warp partial of W_lin . h2
            s->P[wpid][lane] = wl0 * h0 + wl1 * h1 + wl2 * h2 + wl3 * h3;
        }
        __syncthreads();   // S3: h2_new + partials visible

        // warp 12: reduce partials -> out; stage x_{t+1}; prefetch
        if (wpid == NWARP - 1) {
            float a0 = s->P[0][lane], a1 = s->P[1][lane], a2 = s->P[2][lane];
            a0 += s->P[3][lane];  a1 += s->P[4][lane];  a2 += s->P[5][lane];
            a0 += s->P[6][lane];  a1 += s->P[7][lane];  a2 += s->P[8][lane];
            a0 += s->P[9][lane];  a1 += s->P[10][lane]; a2 += s->P[11][lane];
            float o = a0 + a1 + a2 + s->P[12][lane] + blin;
            out_prev = o;
            out[grow * T_TOT + t] = o;
            // stage x for step t+1 into nxt1's x slot (read by GEMM-A next step)
            nxt1[Hh * 32 + lane] = (t + 1 < T_IN) ? xv : out_prev;
            if (t + 2 < T_IN) xv = xin[grow * T_IN + t + 2];
        }
        __syncthreads();   // S1 (of next step): x staged, step complete
    }
}

extern "C" void kernel_launch(void* const* d_in, const int* in_sizes, int n_in,
                              void* d_out, int out_size) {
    (void)in_sizes; (void)n_in; (void)out_size;
    const size_t smem = sizeof(SmemLayout);
    cudaFuncSetAttribute(lstm_seq_kernel, cudaFuncAttributeMaxDynamicSharedMemorySize, (int)smem);
    lstm_seq_kernel<<<NCTA, NTHR, smem>>>(
        (const float*)d_in[0],   // inputs [B, T]
        (const float*)d_in[1],   // W_ih1 [204,1]
        (const float*)d_in[2],   // W_hh1 [204,51]
        (const float*)d_in[3],   // b_ih1 [204]
        (const float*)d_in[4],   // b_hh1 [204]
        (const float*)d_in[5],   // W_ih2 [204,51]
        (const float*)d_in[6],   // W_hh2 [204,51]
        (const float*)d_in[7],   // b_ih2 [204]
        (const float*)d_in[8],   // b_hh2 [204]
        (const float*)d_in[9],   // W_lin [1,51]
        (const float*)d_in[10],  // b_lin [1]
        (float*)d_out);          // out [B, 1100]
}

// round 8
// speedup vs baseline: 1.0411x; 1.0411x over previous
#include <cuda_runtime.h>

// Sequence_53300544143404: 2-layer LSTM (H=51), B=4096, T=1000 + 100 future.
// R7: k-split warp pairs. 26 warps = 13 h-groups x 2 k-halves. Each half-warp
// computes half the K range of its 4-h gate GEMM; the pair exchanges partial
// accumulators via smem + a named pair barrier (bar.sync hg+1, 64), then each
// half does the pointwise update for 2 of the 4 h. Doubles warps/SMSP (3.25 ->
// 6.5) at unchanged per-warp load:fma ratio to fix the R6 latency exposure.
// Weight loads warp-uniform (broadcast), value loads coalesced, folded linear
// head, 3 full barriers/step, f32x2 FMAs, cell state register-resident.

#define Hh    51
#define BATCH 4096
#define T_IN  1000
#define FUT   100
#define T_TOT (T_IN + FUT)
#define NHG   13            // h-groups of 4 h (h 0..51, h=51 zero pad)
#define NWARP (NHG * 2)     // 26 warps: (hgroup, khalf)
#define NTHR  (NWARP * 32)  // 832
#define RPC   32            // batch rows per CTA (= lanes)
#define NCTA  (BATCH / RPC) // 128

typedef unsigned long long ull;

struct SmemLayout {
    // Layer1 weights: [hg][k][16]; 16 = 4 h x 4 gates (i,f,g,o).
    // k 0..50 = W_hh1 columns, k==51 = W_ih1 (x column).
    float WA[NHG][52][16];
    // Layer2: k 0..50 = W_ih2 (h1 input), k==51 = 0 (x slot of B1),
    //         k 52..102 = W_hh2 (h2 input), k==103 = 0 (pad row of B2).
    float WB[NHG][104][16];
    // Ping-pong state buffers: B[p][k][lane]. 128B rows, coalesced.
    float B1[2][52][32];    // k 0..50 = h1, k 51 = x slot
    float B2[2][52][32];    // k 0..50 = h2, k 51 stays zero
    float BA[NHG][16];      // b_ih1 + b_hh1, [4h x 4g]
    float BB[NHG][16];      // b_ih2 + b_hh2
    // Partial-accumulator exchange: [hg][slot][j][lane].
    // slot 0: kh0's partials for h2,h3 (read by kh1)
    // slot 1: kh1's partials for h0,h1 (read by kh0)
    ull   XC[NHG][2][4][32];
    float P[NWARP][32];     // per-warp W_lin partials (2 h each)
};

__device__ __forceinline__ ull ffma2(ull a, ull b, ull c) {
    ull d;
    asm("fma.rn.f32x2 %0, %1, %2, %3;" : "=l"(d) : "l"(a), "l"(b), "l"(c));
    return d;
}
__device__ __forceinline__ ull add2(ull a, ull b) {
    ull d;
    asm("add.rn.f32x2 %0, %1, %2;" : "=l"(d) : "l"(a), "l"(b));
    return d;
}
__device__ __forceinline__ ull pack2(float lo, float hi) {
    ull r; asm("mov.b64 %0, {%1, %2};" : "=l"(r) : "f"(lo), "f"(hi)); return r;
}
__device__ __forceinline__ void unpack2(ull v, float& lo, float& hi) {
    asm("mov.b64 {%0, %1}, %2;" : "=f"(lo), "=f"(hi) : "l"(v));
}
__device__ __forceinline__ float sig_(float x) {
    return __fdividef(1.0f, 1.0f + __expf(-x));
}
__device__ __forceinline__ float tanh_(float x) {
    float a = fabsf(x);
    float e = __expf(-2.0f * a);
    float r = __fdividef(1.0f - e, 1.0f + e);
    return copysignf(r, x);
}
__device__ __forceinline__ float cell_update(ull aIF, ull aGO, float& c) {
    float gi, gf, gg, go;
    unpack2(aIF, gi, gf);
    unpack2(aGO, gg, go);
    float cn = sig_(gf) * c + sig_(gi) * tanh_(gg);
    c = cn;
    return sig_(go) * tanh_(cn);
}

// Accumulators: [h0IF,h0GO,h1IF,h1GO,h2IF,h2GO,h3IF,h3GO]
struct Acc { ull a[8]; };

// nk iterations; per k: 64B warp-uniform weights (4 LDS.128, broadcast),
// 4B/lane value (1 coalesced LDS.32), 1 pack, 8 FFMA2.
__device__ __forceinline__ void gemm_block(const float* w, const float* v, int nk, Acc& A) {
    #pragma unroll 2
    for (int k = 0; k < nk; ++k) {
        ulonglong2 w0 = *reinterpret_cast<const ulonglong2*>(w);       // h0:(i,f),(g,o)
        ulonglong2 w1 = *reinterpret_cast<const ulonglong2*>(w + 4);   // h1
        ulonglong2 w2 = *reinterpret_cast<const ulonglong2*>(w + 8);   // h2
        ulonglong2 w3 = *reinterpret_cast<const ulonglong2*>(w + 12);  // h3
        float vv = *v;
        ull pv = pack2(vv, vv);
        w += 16; v += 32;
        A.a[0] = ffma2(w0.x, pv, A.a[0]);
        A.a[1] = ffma2(w0.y, pv, A.a[1]);
        A.a[2] = ffma2(w1.x, pv, A.a[2]);
        A.a[3] = ffma2(w1.y, pv, A.a[3]);
        A.a[4] = ffma2(w2.x, pv, A.a[4]);
        A.a[5] = ffma2(w2.y, pv, A.a[5]);
        A.a[6] = ffma2(w3.x, pv, A.a[6]);
        A.a[7] = ffma2(w3.y, pv, A.a[7]);
    }
}

extern __shared__ __align__(16) char smem_raw[];

// Exchange partials within the (hg) pair and do the split pointwise update.
// kh0 updates h0,h1 (rows 4hg, 4hg+1); kh1 updates h2,h3 (rows 4hg+2, 4hg+3).
// Returns the two updated h values and stores them to the state buffer.
__device__ __forceinline__ void pair_exchange_update(
    SmemLayout* s, Acc& A, int hg, int kh, int lane,
    float* dst /* state buffer base */, float& cA, float& cB,
    float wlA, float wlB, float* pOut /* P[w] or nullptr-like unused */)
{
    if (kh == 0) {
        s->XC[hg][0][0][lane] = A.a[4];
        s->XC[hg][0][1][lane] = A.a[5];
        s->XC[hg][0][2][lane] = A.a[6];
        s->XC[hg][0][3][lane] = A.a[7];
    } else {
        s->XC[hg][1][0][lane] = A.a[0];
        s->XC[hg][1][1][lane] = A.a[1];
        s->XC[hg][1][2][lane] = A.a[2];
        s->XC[hg][1][3][lane] = A.a[3];
    }
    asm volatile("bar.sync %0, 64;" :: "r"(hg + 1) : "memory");
    float hA, hB;
    if (kh == 0) {
        ull pIF0 = add2(A.a[0], s->XC[hg][1][0][lane]);
        ull pGO0 = add2(A.a[1], s->XC[hg][1][1][lane]);
        ull pIF1 = add2(A.a[2], s->XC[hg][1][2][lane]);
        ull pGO1 = add2(A.a[3], s->XC[hg][1][3][lane]);
        hA = cell_update(pIF0, pGO0, cA);
        hB = cell_update(pIF1, pGO1, cB);
        dst[(4 * hg + 0) * 32 + lane] = hA;
        dst[(4 * hg + 1) * 32 + lane] = hB;
    } else {
        ull pIF2 = add2(A.a[4], s->XC[hg][0][0][lane]);
        ull pGO2 = add2(A.a[5], s->XC[hg][0][1][lane]);
        ull pIF3 = add2(A.a[6], s->XC[hg][0][2][lane]);
        ull pGO3 = add2(A.a[7], s->XC[hg][0][3][lane]);
        hA = cell_update(pIF2, pGO2, cA);
        hB = cell_update(pIF3, pGO3, cB);
        dst[(4 * hg + 2) * 32 + lane] = hA;
        if (4 * hg + 3 < Hh) dst[(4 * hg + 3) * 32 + lane] = hB;
    }
    if (pOut) *pOut = wlA * hA + wlB * hB;
}

__global__ __launch_bounds__(NTHR, 1)
void lstm_seq_kernel(const float* __restrict__ xin,
                     const float* __restrict__ W_ih1, const float* __restrict__ W_hh1,
                     const float* __restrict__ b_ih1, const float* __restrict__ b_hh1,
                     const float* __restrict__ W_ih2, const float* __restrict__ W_hh2,
                     const float* __restrict__ b_ih2, const float* __restrict__ b_hh2,
                     const float* __restrict__ W_lin, const float* __restrict__ b_lin,
                     float* __restrict__ out)
{
    SmemLayout* s = reinterpret_cast<SmemLayout*>(smem_raw);
    const int tid  = threadIdx.x;
    const int lane = tid & 31;
    const int wpid = tid >> 5;          // 0..25
    const int hg   = wpid >> 1;         // 0..12
    const int kh   = wpid & 1;          // k-half
    const int grow = blockIdx.x * RPC + lane;   // global batch row (< BATCH)

    // ---------------- one-time smem staging ----------------
    for (int i = tid; i < NHG * 52 * 16; i += NTHR) {
        int w = i / (52 * 16); int rem = i - w * 52 * 16; int k = rem >> 4; int j = rem & 15;
        int h = 4 * w + (j >> 2); int g = j & 3;
        float v = 0.f;
        if (h < Hh) {
            if (k < Hh)       v = W_hh1[(g * Hh + h) * Hh + k];
            else if (k == Hh) v = W_ih1[g * Hh + h];
        }
        s->WA[w][k][j] = v;
    }
    for (int i = tid; i < NHG * 104 * 16; i += NTHR) {
        int w = i / (104 * 16); int rem = i - w * 104 * 16; int k = rem >> 4; int j = rem & 15;
        int h = 4 * w + (j >> 2); int g = j & 3;
        float v = 0.f;
        if (h < Hh) {
            if (k < Hh)                      v = W_ih2[(g * Hh + h) * Hh + k];
            else if (k >= 52 && k < 52 + Hh) v = W_hh2[(g * Hh + h) * Hh + (k - 52)];
        }
        s->WB[w][k][j] = v;
    }
    for (int i = tid; i < NHG * 16; i += NTHR) {
        int w = i >> 4, j = i & 15;
        int h = 4 * w + (j >> 2); int g = j & 3;
        float a = 0.f, b = 0.f;
        if (h < Hh) {
            a = b_ih1[g * Hh + h] + b_hh1[g * Hh + h];
            b = b_ih2[g * Hh + h] + b_hh2[g * Hh + h];
        }
        s->BA[w][j] = a; s->BB[w][j] = b;
    }
    for (int i = tid; i < 2 * 52 * 32; i += NTHR) {
        s->B1[0][0][i] = 0.f;
        s->B2[0][0][i] = 0.f;
    }

    // W_lin coefficients for this warp's 2 updated h (register-resident)
    const int myh0 = 4 * hg + 2 * kh;
    const int myh1 = myh0 + 1;
    float wlA = (myh0 < Hh) ? W_lin[myh0] : 0.f;
    float wlB = (myh1 < Hh) ? W_lin[myh1] : 0.f;
    float blin = b_lin[0];

    float xv = 0.f;
    if (wpid == NWARP - 1) {
        // stage x[t=0] and prefetch x[t=1]
        s->B1[0][Hh][lane] = xin[grow * T_IN];
        xv = xin[grow * T_IN + 1];
    }
    __syncthreads();

    // k-range bases for this k-half
    const float* waBase = &s->WA[hg][kh * 26][0];        // layer1: 26 k each
    const float* wbBase = &s->WB[hg][kh * 52][0];        // layer2: 52 k each
    const int v1off = kh * 26 * 32;                      // value offset, layer1

    float cA1 = 0.f, cB1 = 0.f;   // layer1 cell states for my 2 h
    float cA2 = 0.f, cB2 = 0.f;   // layer2
    float out_prev = 0.f;

    // ---------------- time loop ----------------
    for (int t = 0; t < T_TOT; ++t) {
        const int p = t & 1;
        const float* cur1 = &s->B1[p][0][0];
        float*       nxt1 = &s->B1[p ^ 1][0][0];
        const float* cur2 = &s->B2[p][0][0];
        float*       nxt2 = &s->B2[p ^ 1][0][0];

        Acc A;
        {
            // gates1 = [W_hh1 | W_ih1] @ [h1; x] + bias1 ; my k-half only
            if (kh == 0) {
                ulonglong2 b0 = *reinterpret_cast<const ulonglong2*>(&s->BA[hg][0]);
                ulonglong2 b1 = *reinterpret_cast<const ulonglong2*>(&s->BA[hg][4]);
                ulonglong2 b2 = *reinterpret_cast<const ulonglong2*>(&s->BA[hg][8]);
                ulonglong2 b3 = *reinterpret_cast<const ulonglong2*>(&s->BA[hg][12]);
                A.a[0] = b0.x; A.a[1] = b0.y; A.a[2] = b1.x; A.a[3] = b1.y;
                A.a[4] = b2.x; A.a[5] = b2.y; A.a[6] = b3.x; A.a[7] = b3.y;
            } else {
                #pragma unroll
                for (int i = 0; i < 8; ++i) A.a[i] = 0ull;
            }
            gemm_block(waBase, cur1 + v1off + lane, 26, A);
            pair_exchange_update(s, A, hg, kh, lane, nxt1, cA1, cB1, 0.f, 0.f, nullptr);
        }
        __syncthreads();   // S2: h1_new visible

        {
            // gates2 = [W_ih2 | W_hh2] @ [h1_new; h2] + bias2
            // kh0 half reads h1_new (nxt1), kh1 half reads h2 (cur2).
            if (kh == 0) {
                ulonglong2 b0 = *reinterpret_cast<const ulonglong2*>(&s->BB[hg][0]);
                ulonglong2 b1 = *reinterpret_cast<const ulonglong2*>(&s->BB[hg][4]);
                ulonglong2 b2 = *reinterpret_cast<const ulonglong2*>(&s->BB[hg][8]);
                ulonglong2 b3 = *reinterpret_cast<const ulonglong2*>(&s->BB[hg][12]);
                A.a[0] = b0.x; A.a[1] = b0.y; A.a[2] = b1.x; A.a[3] = b1.y;
                A.a[4] = b2.x; A.a[5] = b2.y; A.a[6] = b3.x; A.a[7] = b3.y;
                gemm_block(wbBase, nxt1 + lane, 52, A);
            } else {
                #pragma unroll
                for (int i = 0; i < 8; ++i) A.a[i] = 0ull;
                gemm_block(wbBase, cur2 + lane, 52, A);
            }
            pair_exchange_update(s, A, hg, kh, lane, nxt2, cA2, cB2,
                                 wlA, wlB, &s->P[wpid][lane]);
        }
        __syncthreads();   // S3: h2_new + partials visible

        // warp 25: reduce partials -> out; stage x_{t+1}; prefetch
        if (wpid == NWARP - 1) {
            float a0 = s->P[0][lane], a1 = s->P[1][lane];
            #pragma unroll
            for (int w2 = 2; w2 < NWARP; w2 += 2) {
                a0 += s->P[w2][lane];
                a1 += s->P[w2 + 1][lane];
            }
            float o = a0 + a1 + blin;
            out_prev = o;
            out[grow * T_TOT + t] = o;
            // stage x for step t+1 into nxt1's x slot (read by GEMM-A next step)
            nxt1[Hh * 32 + lane] = (t + 1 < T_IN) ? xv : out_prev;
            if (t + 2 < T_IN) xv = xin[grow * T_IN + t + 2];
        }
        __syncthreads();   // S1 (of next step): x staged, step complete
    }
}

extern "C" void kernel_launch(void* const* d_in, const int* in_sizes, int n_in,
                              void* d_out, int out_size) {
    (void)in_sizes; (void)n_in; (void)out_size;
    const size_t smem = sizeof(SmemLayout);
    cudaFuncSetAttribute(lstm_seq_kernel, cudaFuncAttributeMaxDynamicSharedMemorySize, (int)smem);
    lstm_seq_kernel<<<NCTA, NTHR, smem>>>(
        (const float*)d_in[0],   // inputs [B, T]
        (const float*)d_in[1],   // W_ih1 [204,1]
        (const float*)d_in[2],   // W_hh1 [204,51]
        (const float*)d_in[3],   // b_ih1 [204]
        (const float*)d_in[4],   // b_hh1 [204]
        (const float*)d_in[5],   // W_ih2 [204,51]
        (const float*)d_in[6],   // W_hh2 [204,51]
        (const float*)d_in[7],   // b_ih2 [204]
        (const float*)d_in[8],   // b_hh2 [204]
        (const float*)d_in[9],   // W_lin [1,51]
        (const float*)d_in[10],  // b_lin [1]
        (float*)d_out);          // out [B, 1100]
}